// round 1
// baseline (speedup 1.0000x reference)
#include <cuda_runtime.h>
#include <cstdint>

// Problem dims (fixed by reference)
#define BATCH 8192
#define IN    1024
#define OUT   1024
#define P     8

// GEMM tiling
#define BM 128
#define BN 128
#define BK 32
#define KT (IN / BK)     // 32 k-iterations
#define STAGES 3
#define THREADS 256

// 4 MB scratch for the effective weight matrix [OUT, IN] (K-contiguous)
__device__ float g_weff[OUT * IN];

// ---------------------------------------------------------------------------
// Kernel A: w_eff[o,i] = (sum_p coef[o,i,p]) * weights[o,i]
// ---------------------------------------------------------------------------
__global__ void weff_kernel(const float4* __restrict__ coef,
                            const float* __restrict__ w) {
    int i = blockIdx.x * blockDim.x + threadIdx.x;   // 0 .. OUT*IN-1
    float4 c0 = coef[2 * i];
    float4 c1 = coef[2 * i + 1];
    float s = ((c0.x + c0.y) + (c0.z + c0.w)) + ((c1.x + c1.y) + (c1.z + c1.w));
    g_weff[i] = s * w[i];
}

// ---------------------------------------------------------------------------
// Kernel B: C[8192,1024] = X[8192,1024] @ Weff[1024,1024]^T   (TN, fp32 via tf32)
// ---------------------------------------------------------------------------
__device__ __forceinline__ void cp_async16(void* s, const void* g) {
    uint32_t sa = (uint32_t)__cvta_generic_to_shared(s);
    asm volatile("cp.async.cg.shared.global [%0], [%1], 16;\n" :: "r"(sa), "l"(g));
}
__device__ __forceinline__ void cp_commit() {
    asm volatile("cp.async.commit_group;\n");
}
__device__ __forceinline__ void cp_wait1() {
    asm volatile("cp.async.wait_group 1;\n");
}
__device__ __forceinline__ uint32_t f2tf32(float f) {
    uint32_t r;
    asm("cvt.rna.tf32.f32 %0, %1;" : "=r"(r) : "f"(f));
    return r;
}
__device__ __forceinline__ void mma_tf32(float* c, const uint32_t* a, const uint32_t* b) {
    asm volatile(
        "mma.sync.aligned.m16n8k8.row.col.f32.tf32.tf32.f32 "
        "{%0,%1,%2,%3},{%4,%5,%6,%7},{%8,%9},{%0,%1,%2,%3};\n"
        : "+f"(c[0]), "+f"(c[1]), "+f"(c[2]), "+f"(c[3])
        : "r"(a[0]), "r"(a[1]), "r"(a[2]), "r"(a[3]), "r"(b[0]), "r"(b[1]));
}

// Load one BMxBK (and BNxBK) tile stage via cp.async with XOR swizzle.
// Swizzle: within a row of 32 floats (8 groups of 4), group' = group ^ (row & 7).
__device__ __forceinline__ void load_tile(const float* __restrict__ Ag,
                                          const float* __restrict__ Bg,
                                          float* as, float* bs,
                                          int kt, int lr, int lc) {
    int kofs = kt * BK + lc * 4;
#pragma unroll
    for (int j = 0; j < 4; j++) {
        int r = lr + j * 32;
        int sw = (lc ^ (r & 7)) * 4;
        cp_async16(as + r * BK + sw, Ag + (size_t)r * IN + kofs);
        cp_async16(bs + r * BK + sw, Bg + (size_t)r * IN + kofs);
    }
}

__global__ void __launch_bounds__(THREADS, 2)
gemm_tf32(const float* __restrict__ A, float* __restrict__ C) {
    extern __shared__ float smem[];
    float* As = smem;                       // STAGES * BM * BK
    float* Bs = smem + STAGES * BM * BK;    // STAGES * BN * BK

    const int tid    = threadIdx.x;
    const int warpId = tid >> 5;
    const int lane   = tid & 31;
    const int g      = lane >> 2;     // 0..7
    const int t4     = lane & 3;      // 0..3
    const int warpM  = warpId & 1;    // 2 warps in M
    const int warpN  = warpId >> 1;   // 4 warps in N

    const int bm = blockIdx.y * BM;
    const int bn = blockIdx.x * BN;

    const int lr = tid >> 3;   // 0..31 (row for loads)
    const int lc = tid & 7;    // 0..7  (16B group for loads)

    const float* Ag = A + (size_t)bm * IN;
    const float* Bg = g_weff + (size_t)bn * IN;

    float acc[4][4][4];
#pragma unroll
    for (int mi = 0; mi < 4; mi++)
#pragma unroll
        for (int ni = 0; ni < 4; ni++)
#pragma unroll
            for (int k = 0; k < 4; k++) acc[mi][ni][k] = 0.f;

    // Prologue: fill stages 0,1
    load_tile(Ag, Bg, As + 0 * BM * BK, Bs + 0 * BM * BK, 0, lr, lc);
    cp_commit();
    load_tile(Ag, Bg, As + 1 * BM * BK, Bs + 1 * BM * BK, 1, lr, lc);
    cp_commit();

    for (int kt = 0; kt < KT; kt++) {
        cp_wait1();            // data for stage kt%3 is ready
        __syncthreads();       // also protects stage (kt+2)%3 from overwrite

        if (kt + 2 < KT) {
            int s = (kt + 2) % STAGES;
            load_tile(Ag, Bg, As + s * BM * BK, Bs + s * BM * BK, kt + 2, lr, lc);
        }
        cp_commit();           // always commit (possibly empty group)

        const float* as = As + (kt % STAGES) * BM * BK;
        const float* bs = Bs + (kt % STAGES) * BM * BK;

#pragma unroll
        for (int k0 = 0; k0 < BK; k0 += 8) {
            const int kg = k0 >> 2;  // base 16B-group index (two groups per k-step)
            uint32_t af[4][4];
            uint32_t bf[4][2];
#pragma unroll
            for (int mi = 0; mi < 4; mi++) {
                int row  = warpM * 64 + mi * 16 + g;
                int row8 = row + 8;
                af[mi][0] = f2tf32(as[row  * BK + ((kg    ) ^ (row  & 7)) * 4 + t4]);
                af[mi][1] = f2tf32(as[row8 * BK + ((kg    ) ^ (row8 & 7)) * 4 + t4]);
                af[mi][2] = f2tf32(as[row  * BK + ((kg + 1) ^ (row  & 7)) * 4 + t4]);
                af[mi][3] = f2tf32(as[row8 * BK + ((kg + 1) ^ (row8 & 7)) * 4 + t4]);
            }
#pragma unroll
            for (int ni = 0; ni < 4; ni++) {
                int n = warpN * 32 + ni * 8 + g;
                bf[ni][0] = f2tf32(bs[n * BK + ((kg    ) ^ (n & 7)) * 4 + t4]);
                bf[ni][1] = f2tf32(bs[n * BK + ((kg + 1) ^ (n & 7)) * 4 + t4]);
            }
#pragma unroll
            for (int mi = 0; mi < 4; mi++)
#pragma unroll
                for (int ni = 0; ni < 4; ni++)
                    mma_tf32(acc[mi][ni], af[mi], bf[ni]);
        }
    }

    // Epilogue: fp32 stores, float2 per fragment row-pair
#pragma unroll
    for (int mi = 0; mi < 4; mi++) {
#pragma unroll
        for (int ni = 0; ni < 4; ni++) {
            int row = bm + warpM * 64 + mi * 16 + g;
            int col = bn + warpN * 32 + ni * 8 + t4 * 2;
            float2 v01 = make_float2(acc[mi][ni][0], acc[mi][ni][1]);
            float2 v23 = make_float2(acc[mi][ni][2], acc[mi][ni][3]);
            *reinterpret_cast<float2*>(C + (size_t)row * OUT + col)       = v01;
            *reinterpret_cast<float2*>(C + (size_t)(row + 8) * OUT + col) = v23;
        }
    }
}

// ---------------------------------------------------------------------------
// Harness entry
// ---------------------------------------------------------------------------
extern "C" void kernel_launch(void* const* d_in, const int* in_sizes, int n_in,
                              void* d_out, int out_size) {
    const float* x    = (const float*)d_in[0];   // [8192, 1024]
    const float4* coef = (const float4*)d_in[1]; // [1024, 1024, 8] fp32 -> float4 pairs
    const float* w    = (const float*)d_in[2];   // [1024, 1024]
    float* out = (float*)d_out;                  // [8192, 1024]

    (void)in_sizes; (void)n_in; (void)out_size;

    // Kernel A: build w_eff (1M threads)
    weff_kernel<<<(OUT * IN) / 256, 256>>>(coef, w);

    // Kernel B: tf32 GEMM
    static const int smem_bytes = STAGES * (BM + BN) * BK * (int)sizeof(float); // 96 KB
    cudaFuncSetAttribute(gemm_tf32, cudaFuncAttributeMaxDynamicSharedMemorySize, smem_bytes);
    dim3 grid(OUT / BN, BATCH / BM);  // (8, 64)
    gemm_tf32<<<grid, THREADS, smem_bytes>>>(x, out);
}

// round 3
// speedup vs baseline: 1.5953x; 1.5953x over previous
#include <cuda_runtime.h>
#include <cstdint>

// Problem dims
#define BATCH 8192
#define IN    1024
#define OUT   1024

// GEMM tiling
#define BM 128
#define BN 128
#define BK 32
#define KT (IN / BK)      // 32 k-iterations
#define STAGES 3
#define THREADS 256

// Scratch: pre-rounded (tf32-rna) operands, K-contiguous
__device__ float g_weff[OUT * IN];   // [O, I]
__device__ float g_xr[BATCH * IN];   // [B, I]

// ---------------------------------------------------------------------------
// Helpers
// ---------------------------------------------------------------------------
__device__ __forceinline__ uint32_t f2tf32(float f) {
    uint32_t r;
    asm("cvt.rna.tf32.f32 %0, %1;" : "=r"(r) : "f"(f));
    return r;
}
__device__ __forceinline__ void cp_async16(void* s, const void* g) {
    uint32_t sa = (uint32_t)__cvta_generic_to_shared(s);
    asm volatile("cp.async.cg.shared.global [%0], [%1], 16;\n" :: "r"(sa), "l"(g));
}
__device__ __forceinline__ void cp_commit() {
    asm volatile("cp.async.commit_group;\n");
}
__device__ __forceinline__ void cp_wait1() {
    asm volatile("cp.async.wait_group 1;\n");
}
__device__ __forceinline__ void mma_tf32(float* c, const uint32_t* a, const uint32_t* b) {
    asm volatile(
        "mma.sync.aligned.m16n8k8.row.col.f32.tf32.tf32.f32 "
        "{%0,%1,%2,%3},{%4,%5,%6,%7},{%8,%9},{%0,%1,%2,%3};\n"
        : "+f"(c[0]), "+f"(c[1]), "+f"(c[2]), "+f"(c[3])
        : "r"(a[0]), "r"(a[1]), "r"(a[2]), "r"(a[3]), "r"(b[0]), "r"(b[1]));
}

// ---------------------------------------------------------------------------
// Kernel A (prep): round x -> g_xr (tf32-rna), build+round w_eff -> g_weff
// ---------------------------------------------------------------------------
__global__ void prep_kernel(const float4* __restrict__ x4,
                            const float4* __restrict__ coef,
                            const float* __restrict__ w) {
    const int NX4 = BATCH * IN / 4;          // 2M float4s of x
    int idx = blockIdx.x * blockDim.x + threadIdx.x;
    if (idx < NX4) {
        float4 v = x4[idx];
        uint4 r;
        r.x = f2tf32(v.x); r.y = f2tf32(v.y); r.z = f2tf32(v.z); r.w = f2tf32(v.w);
        reinterpret_cast<uint4*>(g_xr)[idx] = r;
    } else {
        int i = idx - NX4;                   // < OUT*IN = 1M
        float4 c0 = coef[2 * i];
        float4 c1 = coef[2 * i + 1];
        float s = ((c0.x + c0.y) + (c0.z + c0.w)) + ((c1.x + c1.y) + (c1.z + c1.w));
        reinterpret_cast<uint32_t*>(g_weff)[i] = f2tf32(s * w[i]);
    }
}

// ---------------------------------------------------------------------------
// Kernel B: C[8192,1024] = Xr @ Weff^T  (TN, tf32 mma.sync, pre-rounded bits)
// ---------------------------------------------------------------------------
// Swizzle: within a row of 32 floats (8 groups of 4), group' = group ^ (row & 7).
__device__ __forceinline__ void load_tile(const float* __restrict__ Ag,
                                          const float* __restrict__ Bg,
                                          float* as, float* bs,
                                          int kt, int lr, int lc) {
    int kofs = kt * BK + lc * 4;
#pragma unroll
    for (int j = 0; j < 4; j++) {
        int r = lr + j * 32;
        int sw = (lc ^ (r & 7)) * 4;
        cp_async16(as + r * BK + sw, Ag + (size_t)r * IN + kofs);
        cp_async16(bs + r * BK + sw, Bg + (size_t)r * IN + kofs);
    }
}

__global__ void __launch_bounds__(THREADS, 2)
gemm_tf32(const float* __restrict__ A, float* __restrict__ C) {
    extern __shared__ float smem[];
    float* As = smem;                       // STAGES * BM * BK
    float* Bs = smem + STAGES * BM * BK;    // STAGES * BN * BK

    const int tid    = threadIdx.x;
    const int warpId = tid >> 5;
    const int lane   = tid & 31;
    const int g      = lane >> 2;     // 0..7
    const int t4     = lane & 3;      // 0..3
    const int warpM  = warpId & 1;    // 2 warps in M
    const int warpN  = warpId >> 1;   // 4 warps in N

    const int bm = blockIdx.y * BM;
    const int bn = blockIdx.x * BN;

    const int lr = tid >> 3;   // 0..31 (row for loads)
    const int lc = tid & 7;    // 0..7  (16B group for loads)

    const float* Ag = A + (size_t)bm * IN;
    const float* Bg = g_weff + (size_t)bn * IN;

    float acc[4][4][4];
#pragma unroll
    for (int mi = 0; mi < 4; mi++)
#pragma unroll
        for (int ni = 0; ni < 4; ni++)
#pragma unroll
            for (int k = 0; k < 4; k++) acc[mi][ni][k] = 0.f;

    // Prologue: fill stages 0,1
    load_tile(Ag, Bg, As + 0 * BM * BK, Bs + 0 * BM * BK, 0, lr, lc);
    cp_commit();
    load_tile(Ag, Bg, As + 1 * BM * BK, Bs + 1 * BM * BK, 1, lr, lc);
    cp_commit();

    for (int kt = 0; kt < KT; kt++) {
        // Wait for stage kt's group (pending <= 1 leaves kt+1 in flight),
        // then barrier so stage (kt+2)%3 (consumed in iter kt-1) is free.
        cp_wait1();
        __syncthreads();

        if (kt + 2 < KT) {
            int s = (kt + 2) % STAGES;
            load_tile(Ag, Bg, As + s * BM * BK, Bs + s * BM * BK, kt + 2, lr, lc);
        }
        cp_commit();   // always commit (possibly empty group) to keep accounting

        // Pre-rounded tf32 bits: no cvt in the mainloop.
        const uint32_t* as = reinterpret_cast<const uint32_t*>(As + (kt % STAGES) * BM * BK);
        const uint32_t* bs = reinterpret_cast<const uint32_t*>(Bs + (kt % STAGES) * BM * BK);

#pragma unroll
        for (int k0 = 0; k0 < BK; k0 += 8) {
            const int kg = k0 >> 2;  // base 16B-group index (two groups per k-step)
            uint32_t af[4][4];
            uint32_t bf[4][2];
#pragma unroll
            for (int mi = 0; mi < 4; mi++) {
                int row  = warpM * 64 + mi * 16 + g;
                int row8 = row + 8;
                af[mi][0] = as[row  * BK + ((kg    ) ^ (row  & 7)) * 4 + t4];
                af[mi][1] = as[row8 * BK + ((kg    ) ^ (row8 & 7)) * 4 + t4];
                af[mi][2] = as[row  * BK + ((kg + 1) ^ (row  & 7)) * 4 + t4];
                af[mi][3] = as[row8 * BK + ((kg + 1) ^ (row8 & 7)) * 4 + t4];
            }
#pragma unroll
            for (int ni = 0; ni < 4; ni++) {
                int n = warpN * 32 + ni * 8 + g;
                bf[ni][0] = bs[n * BK + ((kg    ) ^ (n & 7)) * 4 + t4];
                bf[ni][1] = bs[n * BK + ((kg + 1) ^ (n & 7)) * 4 + t4];
            }
#pragma unroll
            for (int mi = 0; mi < 4; mi++)
#pragma unroll
                for (int ni = 0; ni < 4; ni++)
                    mma_tf32(acc[mi][ni], af[mi], bf[ni]);
        }
    }

    // Epilogue: fp32 stores, float2 per fragment row-pair
#pragma unroll
    for (int mi = 0; mi < 4; mi++) {
#pragma unroll
        for (int ni = 0; ni < 4; ni++) {
            int row = bm + warpM * 64 + mi * 16 + g;
            int col = bn + warpN * 32 + ni * 8 + t4 * 2;
            float2 v01 = make_float2(acc[mi][ni][0], acc[mi][ni][1]);
            float2 v23 = make_float2(acc[mi][ni][2], acc[mi][ni][3]);
            *reinterpret_cast<float2*>(C + (size_t)row * OUT + col)       = v01;
            *reinterpret_cast<float2*>(C + (size_t)(row + 8) * OUT + col) = v23;
        }
    }
}

// ---------------------------------------------------------------------------
// Harness entry
// ---------------------------------------------------------------------------
extern "C" void kernel_launch(void* const* d_in, const int* in_sizes, int n_in,
                              void* d_out, int out_size) {
    const float4* x4   = (const float4*)d_in[0];  // [8192,1024] fp32
    const float4* coef = (const float4*)d_in[1];  // [1024,1024,8] fp32
    const float*  w    = (const float*)d_in[2];   // [1024,1024] fp32
    float* out = (float*)d_out;                   // [8192,1024] fp32
    (void)in_sizes; (void)n_in; (void)out_size;

    // Prep: round x + build w_eff (3M work items)
    const int NX4 = BATCH * IN / 4;               // 2M
    const int NPREP = NX4 + OUT * IN;             // 3M
    prep_kernel<<<NPREP / 256, 256>>>(x4, coef, w);

    // tf32 GEMM
    static const int smem_bytes = STAGES * (BM + BN) * BK * (int)sizeof(float); // 96 KB
    cudaFuncSetAttribute(gemm_tf32, cudaFuncAttributeMaxDynamicSharedMemorySize, smem_bytes);

    const float* xr_dev;
    cudaGetSymbolAddress((void**)&xr_dev, g_xr);
    dim3 grid(OUT / BN, BATCH / BM);  // (8, 64)
    gemm_tf32<<<grid, THREADS, smem_bytes>>>(xr_dev, out);
}

// round 4
// speedup vs baseline: 1.6688x; 1.0461x over previous
#include <cuda_runtime.h>
#include <cstdint>

// Problem dims
#define BATCH 8192
#define IN    1024
#define OUT   1024

// GEMM tiling: block 128x128, 4 warps (2x2), warp tile 64x64
#define BM 128
#define BN 128
#define BK 32
#define KT (IN / BK)      // 32 k-iterations
#define STAGES 3
#define THREADS 128

// Scratch: pre-rounded (tf32-rna) operands, K-contiguous
__device__ float g_weff[OUT * IN];   // [O, I]
__device__ float g_xr[BATCH * IN];   // [B, I]

// ---------------------------------------------------------------------------
// Helpers
// ---------------------------------------------------------------------------
__device__ __forceinline__ uint32_t f2tf32(float f) {
    uint32_t r;
    asm("cvt.rna.tf32.f32 %0, %1;" : "=r"(r) : "f"(f));
    return r;
}
__device__ __forceinline__ void cp_async16(void* s, const void* g) {
    uint32_t sa = (uint32_t)__cvta_generic_to_shared(s);
    asm volatile("cp.async.cg.shared.global [%0], [%1], 16;\n" :: "r"(sa), "l"(g));
}
__device__ __forceinline__ void cp_commit() {
    asm volatile("cp.async.commit_group;\n");
}
__device__ __forceinline__ void cp_wait1() {
    asm volatile("cp.async.wait_group 1;\n");
}
__device__ __forceinline__ void mma_tf32(float* c, const uint32_t* a, const uint32_t* b) {
    asm volatile(
        "mma.sync.aligned.m16n8k8.row.col.f32.tf32.tf32.f32 "
        "{%0,%1,%2,%3},{%4,%5,%6,%7},{%8,%9},{%0,%1,%2,%3};\n"
        : "+f"(c[0]), "+f"(c[1]), "+f"(c[2]), "+f"(c[3])
        : "r"(a[0]), "r"(a[1]), "r"(a[2]), "r"(a[3]), "r"(b[0]), "r"(b[1]));
}

// ---------------------------------------------------------------------------
// Kernel A (prep): round x -> g_xr (tf32-rna), build+round w_eff -> g_weff
// ---------------------------------------------------------------------------
__global__ void prep_kernel(const float4* __restrict__ x4,
                            const float4* __restrict__ coef,
                            const float* __restrict__ w) {
    const int NX4 = BATCH * IN / 4;          // 2M float4s of x
    int idx = blockIdx.x * blockDim.x + threadIdx.x;
    if (idx < NX4) {
        float4 v = x4[idx];
        uint4 r;
        r.x = f2tf32(v.x); r.y = f2tf32(v.y); r.z = f2tf32(v.z); r.w = f2tf32(v.w);
        reinterpret_cast<uint4*>(g_xr)[idx] = r;
    } else {
        int i = idx - NX4;                   // < OUT*IN = 1M
        float4 c0 = coef[2 * i];
        float4 c1 = coef[2 * i + 1];
        float s = ((c0.x + c0.y) + (c0.z + c0.w)) + ((c1.x + c1.y) + (c1.z + c1.w));
        reinterpret_cast<uint32_t*>(g_weff)[i] = f2tf32(s * w[i]);
    }
}

// ---------------------------------------------------------------------------
// Kernel B: C[8192,1024] = Xr @ Weff^T  (TN, tf32 mma.sync)
// ---------------------------------------------------------------------------
// Swizzle: within a row of 32 floats (8 groups of 4), group' = group ^ (row & 7).
__device__ __forceinline__ void load_tile(const float* __restrict__ Ag,
                                          const float* __restrict__ Bg,
                                          float* as, float* bs,
                                          int kt, int lr, int lc) {
    int kofs = kt * BK + lc * 4;
#pragma unroll
    for (int j = 0; j < 8; j++) {           // 128 rows / 16 rows-per-pass
        int r = lr + j * 16;
        int sw = (lc ^ (r & 7)) * 4;
        cp_async16(as + r * BK + sw, Ag + (size_t)r * IN + kofs);
        cp_async16(bs + r * BK + sw, Bg + (size_t)r * IN + kofs);
    }
}

__global__ void __launch_bounds__(THREADS, 2)
gemm_tf32(const float* __restrict__ A, float* __restrict__ C) {
    extern __shared__ float smem[];
    float* As = smem;                       // STAGES * BM * BK
    float* Bs = smem + STAGES * BM * BK;    // STAGES * BN * BK

    const int tid    = threadIdx.x;
    const int warpId = tid >> 5;            // 0..3
    const int lane   = tid & 31;
    const int g      = lane >> 2;     // 0..7
    const int t4     = lane & 3;      // 0..3
    const int warpM  = warpId & 1;    // 2 warps in M
    const int warpN  = warpId >> 1;   // 2 warps in N

    const int bm = blockIdx.y * BM;
    const int bn = blockIdx.x * BN;

    const int lr = tid >> 3;   // 0..15 (row for loads)
    const int lc = tid & 7;    // 0..7  (16B group for loads)

    const float* Ag = A + (size_t)bm * IN;
    const float* Bg = g_weff + (size_t)bn * IN;

    // Warp tile 64x64: 4 M-fragments x 8 N-fragments
    float acc[4][8][4];
#pragma unroll
    for (int mi = 0; mi < 4; mi++)
#pragma unroll
        for (int ni = 0; ni < 8; ni++)
#pragma unroll
            for (int k = 0; k < 4; k++) acc[mi][ni][k] = 0.f;

    // Prologue: fill stages 0,1
    load_tile(Ag, Bg, As + 0 * BM * BK, Bs + 0 * BM * BK, 0, lr, lc);
    cp_commit();
    load_tile(Ag, Bg, As + 1 * BM * BK, Bs + 1 * BM * BK, 1, lr, lc);
    cp_commit();

    for (int kt = 0; kt < KT; kt++) {
        cp_wait1();            // stage kt resident (kt+1 still in flight)
        __syncthreads();       // stage (kt+2)%3 fully consumed by all warps

        if (kt + 2 < KT) {
            int s = (kt + 2) % STAGES;
            load_tile(Ag, Bg, As + s * BM * BK, Bs + s * BM * BK, kt + 2, lr, lc);
        }
        cp_commit();           // keep group accounting uniform

        const uint32_t* as = reinterpret_cast<const uint32_t*>(As + (kt % STAGES) * BM * BK);
        const uint32_t* bs = reinterpret_cast<const uint32_t*>(Bs + (kt % STAGES) * BM * BK);

#pragma unroll
        for (int k0 = 0; k0 < BK; k0 += 8) {
            const int kg = k0 >> 2;  // two 16B groups per 8-k step
            uint32_t af[4][4];
            uint32_t bf[8][2];
#pragma unroll
            for (int mi = 0; mi < 4; mi++) {
                int row  = warpM * 64 + mi * 16 + g;
                int row8 = row + 8;
                af[mi][0] = as[row  * BK + ((kg    ) ^ (row  & 7)) * 4 + t4];
                af[mi][1] = as[row8 * BK + ((kg    ) ^ (row8 & 7)) * 4 + t4];
                af[mi][2] = as[row  * BK + ((kg + 1) ^ (row  & 7)) * 4 + t4];
                af[mi][3] = as[row8 * BK + ((kg + 1) ^ (row8 & 7)) * 4 + t4];
            }
#pragma unroll
            for (int ni = 0; ni < 8; ni++) {
                int n = warpN * 64 + ni * 8 + g;
                bf[ni][0] = bs[n * BK + ((kg    ) ^ (n & 7)) * 4 + t4];
                bf[ni][1] = bs[n * BK + ((kg + 1) ^ (n & 7)) * 4 + t4];
            }
#pragma unroll
            for (int mi = 0; mi < 4; mi++)
#pragma unroll
                for (int ni = 0; ni < 8; ni++)
                    mma_tf32(acc[mi][ni], af[mi], bf[ni]);
        }
    }

    // Epilogue: fp32 stores, float2 per fragment row-pair
#pragma unroll
    for (int mi = 0; mi < 4; mi++) {
#pragma unroll
        for (int ni = 0; ni < 8; ni++) {
            int row = bm + warpM * 64 + mi * 16 + g;
            int col = bn + warpN * 64 + ni * 8 + t4 * 2;
            float2 v01 = make_float2(acc[mi][ni][0], acc[mi][ni][1]);
            float2 v23 = make_float2(acc[mi][ni][2], acc[mi][ni][3]);
            *reinterpret_cast<float2*>(C + (size_t)row * OUT + col)       = v01;
            *reinterpret_cast<float2*>(C + (size_t)(row + 8) * OUT + col) = v23;
        }
    }
}

// ---------------------------------------------------------------------------
// Harness entry
// ---------------------------------------------------------------------------
extern "C" void kernel_launch(void* const* d_in, const int* in_sizes, int n_in,
                              void* d_out, int out_size) {
    const float4* x4   = (const float4*)d_in[0];  // [8192,1024] fp32
    const float4* coef = (const float4*)d_in[1];  // [1024,1024,8] fp32
    const float*  w    = (const float*)d_in[2];   // [1024,1024] fp32
    float* out = (float*)d_out;                   // [8192,1024] fp32
    (void)in_sizes; (void)n_in; (void)out_size;

    // Prep: round x + build w_eff (3M work items)
    const int NX4 = BATCH * IN / 4;               // 2M
    const int NPREP = NX4 + OUT * IN;             // 3M
    prep_kernel<<<NPREP / 256, 256>>>(x4, coef, w);

    // tf32 GEMM
    static const int smem_bytes = STAGES * (BM + BN) * BK * (int)sizeof(float); // 96 KB
    cudaFuncSetAttribute(gemm_tf32, cudaFuncAttributeMaxDynamicSharedMemorySize, smem_bytes);

    const float* xr_dev;
    cudaGetSymbolAddress((void**)&xr_dev, g_xr);
    dim3 grid(OUT / BN, BATCH / BM);  // (8, 64)
    gemm_tf32<<<grid, THREADS, smem_bytes>>>(xr_dev, out);
}

// round 6
// speedup vs baseline: 2.7863x; 1.6696x over previous
#include <cuda_runtime.h>
#include <cuda_fp16.h>
#include <cstdint>

// Problem dims
#define BATCH 8192
#define IN    1024
#define OUT   1024

// GEMM tiling: block 128x128, 4 warps (2x2), warp tile 64x64, fp16 operands
#define BM 128
#define BN 128
#define BKH 64            // K-halves per stage (= 128 bytes per row)
#define KT (IN / BKH)     // 16 k-iterations
#define STAGES 3
#define THREADS 128

// Scratch: fp16-rounded operands, K-contiguous
__device__ __half g_weffh[OUT * IN];   // [O, I]
__device__ __half g_xrh[BATCH * IN];   // [B, I]

// ---------------------------------------------------------------------------
// Helpers
// ---------------------------------------------------------------------------
__device__ __forceinline__ uint32_t h2_bits(__half2 h) {
    return *reinterpret_cast<uint32_t*>(&h);
}
__device__ __forceinline__ void cp_async16(void* s, const void* g) {
    uint32_t sa = (uint32_t)__cvta_generic_to_shared(s);
    asm volatile("cp.async.cg.shared.global [%0], [%1], 16;\n" :: "r"(sa), "l"(g));
}
__device__ __forceinline__ void cp_commit() {
    asm volatile("cp.async.commit_group;\n");
}
__device__ __forceinline__ void cp_wait1() {
    asm volatile("cp.async.wait_group 1;\n");
}
// fp16 MMA, fp32 accumulate: D[16x8] += A[16x16] * B[16x8]
__device__ __forceinline__ void mma_f16(float* c, const uint32_t* a, const uint32_t* b) {
    asm volatile(
        "mma.sync.aligned.m16n8k16.row.col.f32.f16.f16.f32 "
        "{%0,%1,%2,%3},{%4,%5,%6,%7},{%8,%9},{%0,%1,%2,%3};\n"
        : "+f"(c[0]), "+f"(c[1]), "+f"(c[2]), "+f"(c[3])
        : "r"(a[0]), "r"(a[1]), "r"(a[2]), "r"(a[3]), "r"(b[0]), "r"(b[1]));
}

// ---------------------------------------------------------------------------
// Kernel A (prep): round x -> g_xrh (fp16-rn), build+round w_eff -> g_weffh
// ---------------------------------------------------------------------------
__global__ void prep_kernel(const float4* __restrict__ x4,
                            const float4* __restrict__ coef,
                            const float* __restrict__ w) {
    const int NXH = BATCH * IN / 8;          // 1M: each handles 8 floats of x
    int idx = blockIdx.x * blockDim.x + threadIdx.x;
    if (idx < NXH) {
        float4 v0 = x4[2 * idx];
        float4 v1 = x4[2 * idx + 1];
        uint4 out;
        out.x = h2_bits(__floats2half2_rn(v0.x, v0.y));
        out.y = h2_bits(__floats2half2_rn(v0.z, v0.w));
        out.z = h2_bits(__floats2half2_rn(v1.x, v1.y));
        out.w = h2_bits(__floats2half2_rn(v1.z, v1.w));
        reinterpret_cast<uint4*>(g_xrh)[idx] = out;
    } else {
        int i = (idx - NXH) * 2;             // 2 w_eff elements per thread
        float r0, r1;
        {
            float4 c0 = coef[2 * i];
            float4 c1 = coef[2 * i + 1];
            float s = ((c0.x + c0.y) + (c0.z + c0.w)) + ((c1.x + c1.y) + (c1.z + c1.w));
            r0 = s * w[i];
        }
        {
            float4 c0 = coef[2 * (i + 1)];
            float4 c1 = coef[2 * (i + 1) + 1];
            float s = ((c0.x + c0.y) + (c0.z + c0.w)) + ((c1.x + c1.y) + (c1.z + c1.w));
            r1 = s * w[i + 1];
        }
        reinterpret_cast<uint32_t*>(g_weffh)[i / 2] = h2_bits(__floats2half2_rn(r0, r1));
    }
}

// ---------------------------------------------------------------------------
// Kernel B: C[8192,1024] = Xh @ Weffh^T  (TN, fp16 mma.sync m16n8k16)
// ---------------------------------------------------------------------------
// SMEM rows: 128 bytes (64 halves), 8 x 16B groups, swizzle group^=(row&7).
__device__ __forceinline__ void load_tile(const __half* __restrict__ Ag,
                                          const __half* __restrict__ Bg,
                                          __half* as, __half* bs,
                                          int kt, int lr, int lc) {
    int kofs = kt * BKH + lc * 8;            // half index within row
#pragma unroll
    for (int j = 0; j < 8; j++) {            // 128 rows / 16 rows-per-pass
        int r = lr + j * 16;
        int sw = (lc ^ (r & 7)) * 8;         // halves
        cp_async16(as + r * BKH + sw, Ag + (size_t)r * IN + kofs);
        cp_async16(bs + r * BKH + sw, Bg + (size_t)r * IN + kofs);
    }
}

__global__ void __launch_bounds__(THREADS, 2)
gemm_f16(const __half* __restrict__ A, float* __restrict__ C) {
    extern __shared__ __half smem[];
    __half* As = smem;                        // STAGES * BM * BKH halves
    __half* Bs = smem + STAGES * BM * BKH;

    const int tid    = threadIdx.x;
    const int warpId = tid >> 5;              // 0..3
    const int lane   = tid & 31;
    const int g      = lane >> 2;   // 0..7
    const int t4     = lane & 3;    // 0..3
    const int warpM  = warpId & 1;  // 2 warps in M
    const int warpN  = warpId >> 1; // 2 warps in N

    const int bm = blockIdx.y * BM;
    const int bn = blockIdx.x * BN;

    const int lr = tid >> 3;   // 0..15
    const int lc = tid & 7;    // 0..7

    const __half* Ag = A + (size_t)bm * IN;
    const __half* Bg = g_weffh + (size_t)bn * IN;

    // Warp tile 64x64: 4 M-frags x 8 N-frags
    float acc[4][8][4];
#pragma unroll
    for (int mi = 0; mi < 4; mi++)
#pragma unroll
        for (int ni = 0; ni < 8; ni++)
#pragma unroll
            for (int k = 0; k < 4; k++) acc[mi][ni][k] = 0.f;

    // Prologue
    load_tile(Ag, Bg, As + 0 * BM * BKH, Bs + 0 * BM * BKH, 0, lr, lc);
    cp_commit();
    load_tile(Ag, Bg, As + 1 * BM * BKH, Bs + 1 * BM * BKH, 1, lr, lc);
    cp_commit();

    for (int kt = 0; kt < KT; kt++) {
        cp_wait1();            // stage kt resident (kt+1 in flight)
        __syncthreads();       // stage (kt+2)%3 free

        if (kt + 2 < KT) {
            int s = (kt + 2) % STAGES;
            load_tile(Ag, Bg, As + s * BM * BKH, Bs + s * BM * BKH, kt + 2, lr, lc);
        }
        cp_commit();

        // View stage as uint32 (pairs of halves); row stride = 32 uint32.
        const uint32_t* as = reinterpret_cast<const uint32_t*>(As + (kt % STAGES) * BM * BKH);
        const uint32_t* bs = reinterpret_cast<const uint32_t*>(Bs + (kt % STAGES) * BM * BKH);

#pragma unroll
        for (int s = 0; s < 4; s++) {        // four k16 steps per stage
            uint32_t af[4][4];
            uint32_t bf[8][2];
#pragma unroll
            for (int mi = 0; mi < 4; mi++) {
#pragma unroll
                for (int j = 0; j < 4; j++) {
                    int row = warpM * 64 + mi * 16 + g + (j & 1) * 8;
                    int grp = (2 * s + (j >> 1)) ^ (row & 7);
                    af[mi][j] = as[row * 32 + grp * 4 + t4];
                }
            }
#pragma unroll
            for (int ni = 0; ni < 8; ni++) {
#pragma unroll
                for (int j = 0; j < 2; j++) {
                    int n = warpN * 64 + ni * 8 + g;
                    int grp = (2 * s + j) ^ (n & 7);
                    bf[ni][j] = bs[n * 32 + grp * 4 + t4];
                }
            }
#pragma unroll
            for (int mi = 0; mi < 4; mi++)
#pragma unroll
                for (int ni = 0; ni < 8; ni++)
                    mma_f16(acc[mi][ni], af[mi], bf[ni]);
        }
    }

    // Epilogue: fp32 stores
#pragma unroll
    for (int mi = 0; mi < 4; mi++) {
#pragma unroll
        for (int ni = 0; ni < 8; ni++) {
            int row = bm + warpM * 64 + mi * 16 + g;
            int col = bn + warpN * 64 + ni * 8 + t4 * 2;
            float2 v01 = make_float2(acc[mi][ni][0], acc[mi][ni][1]);
            float2 v23 = make_float2(acc[mi][ni][2], acc[mi][ni][3]);
            *reinterpret_cast<float2*>(C + (size_t)row * OUT + col)       = v01;
            *reinterpret_cast<float2*>(C + (size_t)(row + 8) * OUT + col) = v23;
        }
    }
}

// ---------------------------------------------------------------------------
// Harness entry
// ---------------------------------------------------------------------------
extern "C" void kernel_launch(void* const* d_in, const int* in_sizes, int n_in,
                              void* d_out, int out_size) {
    const float4* x4   = (const float4*)d_in[0];  // [8192,1024] fp32
    const float4* coef = (const float4*)d_in[1];  // [1024,1024,8] fp32
    const float*  w    = (const float*)d_in[2];   // [1024,1024] fp32
    float* out = (float*)d_out;                   // [8192,1024] fp32
    (void)in_sizes; (void)n_in; (void)out_size;

    // Prep: 1M x-vector items + 512K w_eff pair items
    const int NXH = BATCH * IN / 8;               // 1M
    const int NPREP = NXH + OUT * IN / 2;         // 1.5M
    prep_kernel<<<(NPREP + 255) / 256, 256>>>(x4, coef, w);

    // fp16 GEMM
    static const int smem_bytes = STAGES * (BM + BN) * BKH * (int)sizeof(__half); // 96 KB
    cudaFuncSetAttribute(gemm_f16, cudaFuncAttributeMaxDynamicSharedMemorySize, smem_bytes);

    const __half* xr_dev;
    cudaGetSymbolAddress((void**)&xr_dev, g_xrh);
    dim3 grid(OUT / BN, BATCH / BM);  // (8, 64)
    gemm_f16<<<grid, THREADS, smem_bytes>>>(xr_dev, out);
}

// round 7
// speedup vs baseline: 2.9966x; 1.0755x over previous
#include <cuda_runtime.h>
#include <cuda_fp16.h>
#include <cstdint>

// Problem dims
#define BATCH 8192
#define IN    1024
#define OUT   1024

// GEMM tiling: block 128x128, 4 warps (2x2), warp tile 64x64, fp16 operands
#define BM 128
#define BN 128
#define BKH 64            // K-halves per stage (= 128 bytes per row)
#define KT (IN / BKH)     // 16 k-iterations
#define STAGES 3
#define THREADS 128

#define STAGE_HALVES ((BM + BN) * BKH)      // per-stage halves (A then B)
#define A_STAGE_BYTES (BM * BKH * 2)        // 16384
#define STAGE_BYTES   (STAGE_HALVES * 2)    // 32768

// Scratch: fp16-rounded operands, K-contiguous
__device__ __half g_weffh[OUT * IN];   // [O, I]
__device__ __half g_xrh[BATCH * IN];   // [B, I]

// ---------------------------------------------------------------------------
// Helpers
// ---------------------------------------------------------------------------
__device__ __forceinline__ uint32_t h2_bits(__half2 h) {
    return *reinterpret_cast<uint32_t*>(&h);
}
__device__ __forceinline__ void cp_async16(void* s, const void* g) {
    uint32_t sa = (uint32_t)__cvta_generic_to_shared(s);
    asm volatile("cp.async.cg.shared.global [%0], [%1], 16;\n" :: "r"(sa), "l"(g));
}
__device__ __forceinline__ void cp_commit() {
    asm volatile("cp.async.commit_group;\n");
}
__device__ __forceinline__ void cp_wait1() {
    asm volatile("cp.async.wait_group 1;\n");
}
__device__ __forceinline__ void ldsm_x4(uint32_t* r, uint32_t saddr) {
    asm volatile("ldmatrix.sync.aligned.m8n8.x4.shared.b16 {%0,%1,%2,%3}, [%4];"
        : "=r"(r[0]), "=r"(r[1]), "=r"(r[2]), "=r"(r[3]) : "r"(saddr));
}
// fp16 MMA, fp32 accumulate: D[16x8] += A[16x16] * B[16x8]
__device__ __forceinline__ void mma_f16(float* c, const uint32_t* a, const uint32_t* b) {
    asm volatile(
        "mma.sync.aligned.m16n8k16.row.col.f32.f16.f16.f32 "
        "{%0,%1,%2,%3},{%4,%5,%6,%7},{%8,%9},{%0,%1,%2,%3};\n"
        : "+f"(c[0]), "+f"(c[1]), "+f"(c[2]), "+f"(c[3])
        : "r"(a[0]), "r"(a[1]), "r"(a[2]), "r"(a[3]), "r"(b[0]), "r"(b[1]));
}

// ---------------------------------------------------------------------------
// Kernel A (prep): round x -> g_xrh (fp16-rn), build+round w_eff -> g_weffh
// ---------------------------------------------------------------------------
__global__ void prep_kernel(const float4* __restrict__ x4,
                            const float4* __restrict__ coef,
                            const float* __restrict__ w) {
    const int NXH = BATCH * IN / 8;          // 1M: each handles 8 floats of x
    int idx = blockIdx.x * blockDim.x + threadIdx.x;
    if (idx < NXH) {
        float4 v0 = x4[2 * idx];
        float4 v1 = x4[2 * idx + 1];
        uint4 out;
        out.x = h2_bits(__floats2half2_rn(v0.x, v0.y));
        out.y = h2_bits(__floats2half2_rn(v0.z, v0.w));
        out.z = h2_bits(__floats2half2_rn(v1.x, v1.y));
        out.w = h2_bits(__floats2half2_rn(v1.z, v1.w));
        reinterpret_cast<uint4*>(g_xrh)[idx] = out;
    } else {
        int i = (idx - NXH) * 2;             // 2 w_eff elements per thread
        float r0, r1;
        {
            float4 c0 = coef[2 * i];
            float4 c1 = coef[2 * i + 1];
            float s = ((c0.x + c0.y) + (c0.z + c0.w)) + ((c1.x + c1.y) + (c1.z + c1.w));
            r0 = s * w[i];
        }
        {
            float4 c0 = coef[2 * (i + 1)];
            float4 c1 = coef[2 * (i + 1) + 1];
            float s = ((c0.x + c0.y) + (c0.z + c0.w)) + ((c1.x + c1.y) + (c1.z + c1.w));
            r1 = s * w[i + 1];
        }
        reinterpret_cast<uint32_t*>(g_weffh)[i / 2] = h2_bits(__floats2half2_rn(r0, r1));
    }
}

// ---------------------------------------------------------------------------
// Kernel B: C[8192,1024] = Xh @ Weffh^T  (TN, fp16 mma.sync + ldmatrix)
// ---------------------------------------------------------------------------
// SMEM rows: 128 bytes (64 halves), 8 x 16B groups, swizzle group^=(row&7).
__device__ __forceinline__ void load_tile(const __half* __restrict__ Ag,
                                          const __half* __restrict__ Bg,
                                          __half* as, __half* bs,
                                          int kt, int lr, int lc) {
    int kofs = kt * BKH + lc * 8;            // half index within row
#pragma unroll
    for (int j = 0; j < 8; j++) {            // 128 rows / 16 rows-per-pass
        int r = lr + j * 16;
        int sw = (lc ^ (r & 7)) * 8;         // halves
        cp_async16(as + r * BKH + sw, Ag + (size_t)r * IN + kofs);
        cp_async16(bs + r * BKH + sw, Bg + (size_t)r * IN + kofs);
    }
}

__global__ void __launch_bounds__(THREADS, 2)
gemm_f16(const __half* __restrict__ A, float* __restrict__ C) {
    extern __shared__ __half smem[];
    __half* As = smem;                        // STAGES * BM * BKH halves
    __half* Bs = smem + STAGES * BM * BKH;

    const int tid    = threadIdx.x;
    const int warpId = tid >> 5;              // 0..3
    const int lane   = tid & 31;
    const int g      = lane >> 2;   // 0..7
    const int t4     = lane & 3;    // 0..3
    const int warpM  = warpId & 1;  // 2 warps in M
    const int warpN  = warpId >> 1; // 2 warps in N

    const int bm = blockIdx.y * BM;
    const int bn = blockIdx.x * BN;

    const int lr = tid >> 3;   // 0..15
    const int lc = tid & 7;    // 0..7

    const __half* Ag = A + (size_t)bm * IN;
    const __half* Bg = g_weffh + (size_t)bn * IN;

    // ldmatrix per-lane byte offsets (relative to stage A / stage B base).
    // j = lane>>3 selects the 8x8 matrix, rw = lane&7 the row within it.
    const int j8 = lane >> 3;
    const int rw = lane & 7;
    uint32_t a_off[4], b_off[4];
#pragma unroll
    for (int mi = 0; mi < 4; mi++) {
        int row = warpM * 64 + mi * 16 + (j8 & 1) * 8 + rw;
        int c   = j8 >> 1;                   // k-half within step
        a_off[mi] = row * 128 + ((c ^ (row & 7)) * 16);
    }
#pragma unroll
    for (int nj = 0; nj < 4; nj++) {
        int n = warpN * 64 + nj * 16 + (j8 >> 1) * 8 + rw;
        int c = j8 & 1;
        b_off[nj] = n * 128 + ((c ^ (n & 7)) * 16);
    }
    const uint32_t smem_base = (uint32_t)__cvta_generic_to_shared(smem);

    // Warp tile 64x64: 4 M-frags x 8 N-frags
    float acc[4][8][4];
#pragma unroll
    for (int mi = 0; mi < 4; mi++)
#pragma unroll
        for (int ni = 0; ni < 8; ni++)
#pragma unroll
            for (int k = 0; k < 4; k++) acc[mi][ni][k] = 0.f;

    // Prologue
    load_tile(Ag, Bg, As + 0 * BM * BKH, Bs + 0 * BM * BKH, 0, lr, lc);
    cp_commit();
    load_tile(Ag, Bg, As + 1 * BM * BKH, Bs + 1 * BM * BKH, 1, lr, lc);
    cp_commit();

    for (int kt = 0; kt < KT; kt++) {
        cp_wait1();            // stage kt resident (kt+1 in flight)
        __syncthreads();       // stage (kt+2)%3 free

        if (kt + 2 < KT) {
            int s = (kt + 2) % STAGES;
            load_tile(Ag, Bg, As + s * BM * BKH, Bs + s * BM * BKH, kt + 2, lr, lc);
        }
        cp_commit();

        const uint32_t a_base = smem_base + (kt % STAGES) * A_STAGE_BYTES;
        const uint32_t b_base = smem_base + STAGES * A_STAGE_BYTES
                                          + (kt % STAGES) * (BN * BKH * 2);

#pragma unroll
        for (int s = 0; s < 4; s++) {        // four k16 steps per stage
            const uint32_t sx = s * 32;      // XORs into the 16B-group bits
            uint32_t af[4][4];
            uint32_t bf[8][2];
#pragma unroll
            for (int mi = 0; mi < 4; mi++)
                ldsm_x4(af[mi], a_base + (a_off[mi] ^ sx));
#pragma unroll
            for (int nj = 0; nj < 4; nj++) {
                uint32_t r[4];
                ldsm_x4(r, b_base + (b_off[nj] ^ sx));
                bf[2 * nj][0]     = r[0];
                bf[2 * nj][1]     = r[1];
                bf[2 * nj + 1][0] = r[2];
                bf[2 * nj + 1][1] = r[3];
            }
#pragma unroll
            for (int mi = 0; mi < 4; mi++)
#pragma unroll
                for (int ni = 0; ni < 8; ni++)
                    mma_f16(acc[mi][ni], af[mi], bf[ni]);
        }
    }

    // Epilogue: fp32 stores
#pragma unroll
    for (int mi = 0; mi < 4; mi++) {
#pragma unroll
        for (int ni = 0; ni < 8; ni++) {
            int row = bm + warpM * 64 + mi * 16 + g;
            int col = bn + warpN * 64 + ni * 8 + t4 * 2;
            float2 v01 = make_float2(acc[mi][ni][0], acc[mi][ni][1]);
            float2 v23 = make_float2(acc[mi][ni][2], acc[mi][ni][3]);
            *reinterpret_cast<float2*>(C + (size_t)row * OUT + col)       = v01;
            *reinterpret_cast<float2*>(C + (size_t)(row + 8) * OUT + col) = v23;
        }
    }
}

// ---------------------------------------------------------------------------
// Harness entry
// ---------------------------------------------------------------------------
extern "C" void kernel_launch(void* const* d_in, const int* in_sizes, int n_in,
                              void* d_out, int out_size) {
    const float4* x4   = (const float4*)d_in[0];  // [8192,1024] fp32
    const float4* coef = (const float4*)d_in[1];  // [1024,1024,8] fp32
    const float*  w    = (const float*)d_in[2];   // [1024,1024] fp32
    float* out = (float*)d_out;                   // [8192,1024] fp32
    (void)in_sizes; (void)n_in; (void)out_size;

    // Prep: 1M x-vector items + 512K w_eff pair items
    const int NXH = BATCH * IN / 8;               // 1M
    const int NPREP = NXH + OUT * IN / 2;         // 1.5M
    prep_kernel<<<(NPREP + 255) / 256, 256>>>(x4, coef, w);

    // fp16 GEMM
    static const int smem_bytes = STAGES * (BM + BN) * BKH * (int)sizeof(__half); // 96 KB
    cudaFuncSetAttribute(gemm_f16, cudaFuncAttributeMaxDynamicSharedMemorySize, smem_bytes);

    const __half* xr_dev;
    cudaGetSymbolAddress((void**)&xr_dev, g_xrh);
    dim3 grid(OUT / BN, BATCH / BM);  // (8, 64)
    gemm_f16<<<grid, THREADS, smem_bytes>>>(xr_dev, out);
}

// round 8
// speedup vs baseline: 3.0199x; 1.0078x over previous
#include <cuda_runtime.h>
#include <cuda_fp16.h>
#include <cstdint>

// Problem dims
#define BATCH 8192
#define IN    1024
#define OUT   1024

// GEMM tiling: block 128x128, 8 warps (2M x 4N), warp tile 64x32, fp16
#define BM 128
#define BN 128
#define BKH 64            // K-halves per stage (= 128 bytes per row)
#define KT (IN / BKH)     // 16 k-iterations
#define STAGES 3
#define THREADS 256

#define A_STAGE_BYTES (BM * BKH * 2)        // 16384
#define B_STAGE_BYTES (BN * BKH * 2)        // 16384

// Scratch: fp16-rounded operands, K-contiguous
__device__ __half g_weffh[OUT * IN];   // [O, I]
__device__ __half g_xrh[BATCH * IN];   // [B, I]

// ---------------------------------------------------------------------------
// Helpers
// ---------------------------------------------------------------------------
__device__ __forceinline__ uint32_t h2_bits(__half2 h) {
    return *reinterpret_cast<uint32_t*>(&h);
}
__device__ __forceinline__ void cp_async16(void* s, const void* g) {
    uint32_t sa = (uint32_t)__cvta_generic_to_shared(s);
    asm volatile("cp.async.cg.shared.global [%0], [%1], 16;\n" :: "r"(sa), "l"(g));
}
__device__ __forceinline__ void cp_commit() {
    asm volatile("cp.async.commit_group;\n");
}
__device__ __forceinline__ void cp_wait1() {
    asm volatile("cp.async.wait_group 1;\n");
}
__device__ __forceinline__ void ldsm_x4(uint32_t* r, uint32_t saddr) {
    asm volatile("ldmatrix.sync.aligned.m8n8.x4.shared.b16 {%0,%1,%2,%3}, [%4];"
        : "=r"(r[0]), "=r"(r[1]), "=r"(r[2]), "=r"(r[3]) : "r"(saddr));
}
// fp16 MMA, fp32 accumulate: D[16x8] += A[16x16] * B[16x8]
__device__ __forceinline__ void mma_f16(float* c, const uint32_t* a, const uint32_t* b) {
    asm volatile(
        "mma.sync.aligned.m16n8k16.row.col.f32.f16.f16.f32 "
        "{%0,%1,%2,%3},{%4,%5,%6,%7},{%8,%9},{%0,%1,%2,%3};\n"
        : "+f"(c[0]), "+f"(c[1]), "+f"(c[2]), "+f"(c[3])
        : "r"(a[0]), "r"(a[1]), "r"(a[2]), "r"(a[3]), "r"(b[0]), "r"(b[1]));
}

// ---------------------------------------------------------------------------
// Kernel A (prep): round x -> g_xrh (fp16-rn), build+round w_eff -> g_weffh
// ---------------------------------------------------------------------------
__global__ void prep_kernel(const float4* __restrict__ x4,
                            const float4* __restrict__ coef,
                            const float* __restrict__ w) {
    const int NXH = BATCH * IN / 8;          // 1M: each handles 8 floats of x
    int idx = blockIdx.x * blockDim.x + threadIdx.x;
    if (idx < NXH) {
        float4 v0 = x4[2 * idx];
        float4 v1 = x4[2 * idx + 1];
        uint4 out;
        out.x = h2_bits(__floats2half2_rn(v0.x, v0.y));
        out.y = h2_bits(__floats2half2_rn(v0.z, v0.w));
        out.z = h2_bits(__floats2half2_rn(v1.x, v1.y));
        out.w = h2_bits(__floats2half2_rn(v1.z, v1.w));
        reinterpret_cast<uint4*>(g_xrh)[idx] = out;
    } else {
        int i = (idx - NXH) * 2;             // 2 w_eff elements per thread
        float r0, r1;
        {
            float4 c0 = coef[2 * i];
            float4 c1 = coef[2 * i + 1];
            float s = ((c0.x + c0.y) + (c0.z + c0.w)) + ((c1.x + c1.y) + (c1.z + c1.w));
            r0 = s * w[i];
        }
        {
            float4 c0 = coef[2 * (i + 1)];
            float4 c1 = coef[2 * (i + 1) + 1];
            float s = ((c0.x + c0.y) + (c0.z + c0.w)) + ((c1.x + c1.y) + (c1.z + c1.w));
            r1 = s * w[i + 1];
        }
        reinterpret_cast<uint32_t*>(g_weffh)[i / 2] = h2_bits(__floats2half2_rn(r0, r1));
    }
}

// ---------------------------------------------------------------------------
// Kernel B: C[8192,1024] = Xh @ Weffh^T  (TN, fp16 mma.sync + ldmatrix,
//           register-double-buffered fragments)
// ---------------------------------------------------------------------------
// SMEM rows: 128 bytes (64 halves), 8 x 16B groups, swizzle group^=(row&7).
__device__ __forceinline__ void load_tile(const __half* __restrict__ Ag,
                                          const __half* __restrict__ Bg,
                                          __half* as, __half* bs,
                                          int kt, int lr, int lc) {
    int kofs = kt * BKH + lc * 8;            // half index within row
#pragma unroll
    for (int j = 0; j < 4; j++) {            // 128 rows / 32 rows-per-pass
        int r = lr + j * 32;
        int sw = (lc ^ (r & 7)) * 8;         // halves
        cp_async16(as + r * BKH + sw, Ag + (size_t)r * IN + kofs);
        cp_async16(bs + r * BKH + sw, Bg + (size_t)r * IN + kofs);
    }
}

__global__ void __launch_bounds__(THREADS, 2)
gemm_f16(const __half* __restrict__ A, float* __restrict__ C) {
    extern __shared__ __half smem[];
    __half* As = smem;                        // STAGES * BM * BKH halves
    __half* Bs = smem + STAGES * BM * BKH;

    const int tid    = threadIdx.x;
    const int warpId = tid >> 5;              // 0..7
    const int lane   = tid & 31;
    const int g      = lane >> 2;   // 0..7
    const int t4     = lane & 3;    // 0..3
    const int warpM  = warpId & 1;  // 2 warps in M (64 rows each)
    const int warpN  = warpId >> 1; // 4 warps in N (32 cols each)

    const int bm = blockIdx.y * BM;
    const int bn = blockIdx.x * BN;

    const int lr = tid >> 3;   // 0..31
    const int lc = tid & 7;    // 0..7

    const __half* Ag = A + (size_t)bm * IN;
    const __half* Bg = g_weffh + (size_t)bn * IN;

    // ldmatrix per-lane byte offsets (relative to stage A / stage B base).
    const int j8 = lane >> 3;   // which 8x8 matrix of the x4
    const int rw = lane & 7;    // row within it
    uint32_t a_off[4], b_off[2];
#pragma unroll
    for (int mi = 0; mi < 4; mi++) {
        int row = warpM * 64 + mi * 16 + (j8 & 1) * 8 + rw;
        int c   = j8 >> 1;                   // k-half within step
        a_off[mi] = row * 128 + ((c ^ (row & 7)) * 16);
    }
#pragma unroll
    for (int nj = 0; nj < 2; nj++) {
        int n = warpN * 32 + nj * 16 + (j8 >> 1) * 8 + rw;
        int c = j8 & 1;
        b_off[nj] = n * 128 + ((c ^ (n & 7)) * 16);
    }
    const uint32_t smem_base = (uint32_t)__cvta_generic_to_shared(smem);

    // Warp tile 64x32: 4 M-frags x 4 N-frags
    float acc[4][4][4];
#pragma unroll
    for (int mi = 0; mi < 4; mi++)
#pragma unroll
        for (int ni = 0; ni < 4; ni++)
#pragma unroll
            for (int k = 0; k < 4; k++) acc[mi][ni][k] = 0.f;

    // Prologue
    load_tile(Ag, Bg, As + 0 * BM * BKH, Bs + 0 * BM * BKH, 0, lr, lc);
    cp_commit();
    load_tile(Ag, Bg, As + 1 * BM * BKH, Bs + 1 * BM * BKH, 1, lr, lc);
    cp_commit();

    for (int kt = 0; kt < KT; kt++) {
        cp_wait1();            // stage kt resident (kt+1 in flight)
        __syncthreads();       // stage (kt+2)%3 free

        if (kt + 2 < KT) {
            int s = (kt + 2) % STAGES;
            load_tile(Ag, Bg, As + s * BM * BKH, Bs + s * BM * BKH, kt + 2, lr, lc);
        }
        cp_commit();

        const uint32_t a_base = smem_base + (kt % STAGES) * A_STAGE_BYTES;
        const uint32_t b_base = smem_base + STAGES * A_STAGE_BYTES
                                          + (kt % STAGES) * B_STAGE_BYTES;

        // Register double-buffered fragments: prefetch step s+1 before MMAs of s
        uint32_t af[2][4][4];
        uint32_t bf[2][4][2];
#pragma unroll
        for (int mi = 0; mi < 4; mi++)
            ldsm_x4(af[0][mi], a_base + a_off[mi]);
#pragma unroll
        for (int nj = 0; nj < 2; nj++) {
            uint32_t r[4];
            ldsm_x4(r, b_base + b_off[nj]);
            bf[0][2 * nj][0]     = r[0];
            bf[0][2 * nj][1]     = r[1];
            bf[0][2 * nj + 1][0] = r[2];
            bf[0][2 * nj + 1][1] = r[3];
        }

#pragma unroll
        for (int s = 0; s < 4; s++) {        // four k16 steps per stage
            const int cur = s & 1;
            const int nxt = cur ^ 1;
            if (s < 3) {
                const uint32_t sx = (uint32_t)(s + 1) * 32;
#pragma unroll
                for (int mi = 0; mi < 4; mi++)
                    ldsm_x4(af[nxt][mi], a_base + (a_off[mi] ^ sx));
#pragma unroll
                for (int nj = 0; nj < 2; nj++) {
                    uint32_t r[4];
                    ldsm_x4(r, b_base + (b_off[nj] ^ sx));
                    bf[nxt][2 * nj][0]     = r[0];
                    bf[nxt][2 * nj][1]     = r[1];
                    bf[nxt][2 * nj + 1][0] = r[2];
                    bf[nxt][2 * nj + 1][1] = r[3];
                }
            }
#pragma unroll
            for (int mi = 0; mi < 4; mi++)
#pragma unroll
                for (int ni = 0; ni < 4; ni++)
                    mma_f16(acc[mi][ni], af[cur][mi], bf[cur][ni]);
        }
    }

    // Epilogue: fp32 stores
#pragma unroll
    for (int mi = 0; mi < 4; mi++) {
#pragma unroll
        for (int ni = 0; ni < 4; ni++) {
            int row = bm + warpM * 64 + mi * 16 + g;
            int col = bn + warpN * 32 + ni * 8 + t4 * 2;
            float2 v01 = make_float2(acc[mi][ni][0], acc[mi][ni][1]);
            float2 v23 = make_float2(acc[mi][ni][2], acc[mi][ni][3]);
            *reinterpret_cast<float2*>(C + (size_t)row * OUT + col)       = v01;
            *reinterpret_cast<float2*>(C + (size_t)(row + 8) * OUT + col) = v23;
        }
    }
}

// ---------------------------------------------------------------------------
// Harness entry
// ---------------------------------------------------------------------------
extern "C" void kernel_launch(void* const* d_in, const int* in_sizes, int n_in,
                              void* d_out, int out_size) {
    const float4* x4   = (const float4*)d_in[0];  // [8192,1024] fp32
    const float4* coef = (const float4*)d_in[1];  // [1024,1024,8] fp32
    const float*  w    = (const float*)d_in[2];   // [1024,1024] fp32
    float* out = (float*)d_out;                   // [8192,1024] fp32
    (void)in_sizes; (void)n_in; (void)out_size;

    // Prep: 1M x-vector items + 512K w_eff pair items
    const int NXH = BATCH * IN / 8;               // 1M
    const int NPREP = NXH + OUT * IN / 2;         // 1.5M
    prep_kernel<<<(NPREP + 255) / 256, 256>>>(x4, coef, w);

    // fp16 GEMM
    static const int smem_bytes = STAGES * (BM + BN) * BKH * (int)sizeof(__half); // 96 KB
    cudaFuncSetAttribute(gemm_f16, cudaFuncAttributeMaxDynamicSharedMemorySize, smem_bytes);

    const __half* xr_dev;
    cudaGetSymbolAddress((void**)&xr_dev, g_xrh);
    dim3 grid(OUT / BN, BATCH / BM);  // (8, 64)
    gemm_f16<<<grid, THREADS, smem_bytes>>>(xr_dev, out);
}